// round 2
// baseline (speedup 1.0000x reference)
#include <cuda_runtime.h>

// Problem: ScatterLoss — per-class contrastive hinge loss.
// Inputs: d_in[0] = output [N, D] float32 (N=65536, D=512)
//         d_in[1] = label_id [N] int32 (JAX default x64-disabled downcasts int64)
// Output: scalar float32.
//
// loss = (1/N) * sum_k cnt_k * relu(1 - || s_k/c_k - (T - s_k)/(N - c_k) + 1e-6 ||_2)^2

#define NCLS 512
#define DDIM 512
#define CAP  1024   // max rows per class list (counts ~128 +- 11; 1024 is >30 sigma safe)

static __device__ int   g_cnt[NCLS];
static __device__ int   g_idx[NCLS * CAP];
static __device__ float g_sums[NCLS * DDIM];
static __device__ float g_total[DDIM];
static __device__ float g_lossw[NCLS];

// ---------------------------------------------------------------------------
// K0: zero per-class counters (must reset every launch — graph replays).
// ---------------------------------------------------------------------------
__global__ void k_zero()
{
    g_cnt[threadIdx.x] = 0;
}

// ---------------------------------------------------------------------------
// K1: counting-sort scatter — build per-class row-index lists.
// Labels are int32 (JAX x64 disabled). Range-check defends against bad data.
// ---------------------------------------------------------------------------
__global__ void k_scatter(const int* __restrict__ lab, int N)
{
    int i = blockIdx.x * blockDim.x + threadIdx.x;
    if (i < N) {
        int k = lab[i];
        if (k >= 0 && k < NCLS) {
            int pos = atomicAdd(&g_cnt[k], 1);
            if (pos < CAP) g_idx[k * CAP + pos] = i;
        }
    }
}

// ---------------------------------------------------------------------------
// K2: per-class sum. One block per class; gathers its rows (2KB contiguous
// each, coalesced float4) and accumulates in registers. Dominant kernel:
// reads the full 128 MB matrix exactly once -> HBM bound.
// 256 threads: q = lane-over-columns (128 x float4 = 512 floats),
//              sub = which half of the row list.
// ---------------------------------------------------------------------------
__global__ void __launch_bounds__(256) k_class_sum(const float* __restrict__ out)
{
    __shared__ int    srows[CAP];
    __shared__ float4 sh[128];

    int k  = blockIdx.x;
    int nk = min(g_cnt[k], CAP);

    for (int j = threadIdx.x; j < nk; j += blockDim.x)
        srows[j] = g_idx[k * CAP + j];
    __syncthreads();

    int q   = threadIdx.x & 127;
    int sub = threadIdx.x >> 7;

    float4 acc = make_float4(0.f, 0.f, 0.f, 0.f);
    #pragma unroll 4
    for (int j = sub; j < nk; j += 2) {
        const float4* row = (const float4*)(out + (size_t)srows[j] * DDIM);
        float4 v = __ldg(row + q);
        acc.x += v.x; acc.y += v.y; acc.z += v.z; acc.w += v.w;
    }

    if (sub == 1) sh[q] = acc;
    __syncthreads();
    if (sub == 0) {
        float4 b = sh[q];
        acc.x += b.x; acc.y += b.y; acc.z += b.z; acc.w += b.w;
        ((float4*)(g_sums + (size_t)k * DDIM))[q] = acc;
    }
}

// ---------------------------------------------------------------------------
// K3a: grand total T[d] = sum_k s[k][d].  1 MB, L2-resident after K2.
// ---------------------------------------------------------------------------
__global__ void k_total()
{
    int d = blockIdx.x * 64 + threadIdx.x;
    float s = 0.f;
    #pragma unroll 8
    for (int k = 0; k < NCLS; k++)
        s += g_sums[k * DDIM + d];
    g_total[d] = s;
}

// ---------------------------------------------------------------------------
// K3b: per-class hinge loss, weighted by count. One block (128 thr) per class.
// ---------------------------------------------------------------------------
__global__ void k_loss(float fN)
{
    __shared__ float red[128];
    int k = blockIdx.x;
    int t = threadIdx.x;
    int c = g_cnt[k];

    float partial = 0.f;
    if (c > 0) {
        float fc  = (float)c;
        float ip  = 1.f / fc;
        float in_ = 1.f / (fN - fc);
        float4 s = ((const float4*)(g_sums + (size_t)k * DDIM))[t];
        float4 T = ((const float4*)g_total)[t];
        float dx = s.x * ip - (T.x - s.x) * in_ + 1e-6f;
        float dy = s.y * ip - (T.y - s.y) * in_ + 1e-6f;
        float dz = s.z * ip - (T.z - s.z) * in_ + 1e-6f;
        float dw = s.w * ip - (T.w - s.w) * in_ + 1e-6f;
        partial = dx * dx + dy * dy + dz * dz + dw * dw;
    }

    red[t] = partial;
    __syncthreads();
    #pragma unroll
    for (int s2 = 64; s2 > 0; s2 >>= 1) {
        if (t < s2) red[t] += red[t + s2];
        __syncthreads();
    }
    if (t == 0) {
        float dist = sqrtf(red[0]);
        float m = fmaxf(1.0f - dist, 0.f);   // MARGIN = 1.0
        g_lossw[k] = (c > 0) ? (float)c * m * m : 0.f;
    }
}

// ---------------------------------------------------------------------------
// K3c: deterministic final reduction of 512 class losses -> scalar mean.
// ---------------------------------------------------------------------------
__global__ void k_final(float* __restrict__ out, float fN)
{
    __shared__ float red[NCLS];
    int t = threadIdx.x;
    red[t] = g_lossw[t];
    __syncthreads();
    #pragma unroll
    for (int s = NCLS / 2; s > 0; s >>= 1) {
        if (t < s) red[t] += red[t + s];
        __syncthreads();
    }
    if (t == 0) out[0] = red[0] / fN;
}

// ---------------------------------------------------------------------------
extern "C" void kernel_launch(void* const* d_in, const int* in_sizes, int n_in,
                              void* d_out, int out_size)
{
    const float* output = (const float*)d_in[0];
    const int*   label  = (const int*)d_in[1];
    int N = in_sizes[1];              // 65536 ; D = in_sizes[0]/N = 512 (hardcoded)

    k_zero<<<1, NCLS>>>();
    k_scatter<<<(N + 255) / 256, 256>>>(label, N);
    k_class_sum<<<NCLS, 256>>>(output);
    k_total<<<DDIM / 64, 64>>>();
    k_loss<<<NCLS, 128>>>((float)N);
    k_final<<<1, NCLS>>>((float*)d_out, (float)N);
}

// round 3
// speedup vs baseline: 1.3458x; 1.3458x over previous
#include <cuda_runtime.h>

// ScatterLoss — per-class contrastive hinge loss.
// d_in[0] = output [N, D] float32 (N=65536, D=512)
// d_in[1] = label_id [N] int32
// out     = scalar float32
//
// loss = (1/N) * sum_k cnt_k * relu(1 - || s_k/c_k - (T - s_k)/(N - c_k) + 1e-6 ||_2)^2

#define NCLS 512
#define DDIM 512
#define CAP  1024      // max rows per class (counts ~128±11)
#define TSLB 16        // slabs for the two-stage grand-total reduction

static __device__ int   g_cnt[NCLS];
static __device__ int   g_idx[NCLS * CAP];
static __device__ float g_sums[NCLS * DDIM];
static __device__ float g_totpart[TSLB][DDIM];
static __device__ float g_lossw[NCLS];

// ---------------------------------------------------------------------------
// K0: zero per-class counters (graph replays need reset every launch).
// ---------------------------------------------------------------------------
__global__ void k_zero()
{
    g_cnt[threadIdx.x] = 0;
}

// ---------------------------------------------------------------------------
// K1: counting-sort scatter — per-class row-index lists.
// ---------------------------------------------------------------------------
__global__ void k_scatter(const int* __restrict__ lab, int N)
{
    int i = blockIdx.x * blockDim.x + threadIdx.x;
    if (i < N) {
        int k = lab[i];
        if (k >= 0 && k < NCLS) {
            int pos = atomicAdd(&g_cnt[k], 1);
            if (pos < CAP) g_idx[k * CAP + pos] = i;
        }
    }
}

// ---------------------------------------------------------------------------
// K2: per-class sum. One block per class; coalesced float4 gather of its rows.
// Reads the full 128 MB matrix exactly once -> HBM bound (dominant kernel).
// ---------------------------------------------------------------------------
__global__ void __launch_bounds__(256) k_class_sum(const float* __restrict__ out)
{
    __shared__ int    srows[CAP];
    __shared__ float4 sh[128];

    int k  = blockIdx.x;
    int nk = min(g_cnt[k], CAP);

    for (int j = threadIdx.x; j < nk; j += blockDim.x)
        srows[j] = g_idx[k * CAP + j];
    __syncthreads();

    int q   = threadIdx.x & 127;
    int sub = threadIdx.x >> 7;

    float4 acc = make_float4(0.f, 0.f, 0.f, 0.f);
    #pragma unroll 4
    for (int j = sub; j < nk; j += 2) {
        const float4* row = (const float4*)(out + (size_t)srows[j] * DDIM);
        float4 v = __ldg(row + q);
        acc.x += v.x; acc.y += v.y; acc.z += v.z; acc.w += v.w;
    }

    if (sub == 1) sh[q] = acc;
    __syncthreads();
    if (sub == 0) {
        float4 b = sh[q];
        acc.x += b.x; acc.y += b.y; acc.z += b.z; acc.w += b.w;
        ((float4*)(g_sums + (size_t)k * DDIM))[q] = acc;
    }
}

// ---------------------------------------------------------------------------
// K3a: partial grand totals. 16 blocks x 128 threads; block b sums classes
// [b*32, b*32+32) for all 512 columns (thread = one float4 column group).
// Deep unroll -> high MLP; latency fully overlapped across 64 warps.
// ---------------------------------------------------------------------------
__global__ void __launch_bounds__(128) k_total_part()
{
    int b = blockIdx.x;            // slab
    int t = threadIdx.x;           // float4 column index 0..127
    const int kper = NCLS / TSLB;  // 32

    float4 acc = make_float4(0.f, 0.f, 0.f, 0.f);
    const float4* base = (const float4*)g_sums + (size_t)(b * kper) * 128 + t;
    #pragma unroll 32
    for (int j = 0; j < kper; j++) {
        float4 v = __ldg(base + (size_t)j * 128);
        acc.x += v.x; acc.y += v.y; acc.z += v.z; acc.w += v.w;
    }
    ((float4*)g_totpart[b])[t] = acc;
}

// ---------------------------------------------------------------------------
// K3b: per-class hinge loss, weighted by count. One block (128 thr) per class.
// Folds the 16 grand-total partials (L2-resident) on the fly.
// ---------------------------------------------------------------------------
__global__ void __launch_bounds__(128) k_loss(float fN)
{
    __shared__ float red[128];
    int k = blockIdx.x;
    int t = threadIdx.x;
    int c = g_cnt[k];

    float partial = 0.f;
    if (c > 0) {
        float4 T = make_float4(0.f, 0.f, 0.f, 0.f);
        #pragma unroll
        for (int s = 0; s < TSLB; s++) {
            float4 p = ((const float4*)g_totpart[s])[t];
            T.x += p.x; T.y += p.y; T.z += p.z; T.w += p.w;
        }
        float fc  = (float)c;
        float ip  = 1.f / fc;
        float in_ = 1.f / (fN - fc);
        float4 s = ((const float4*)(g_sums + (size_t)k * DDIM))[t];
        float dx = s.x * ip - (T.x - s.x) * in_ + 1e-6f;
        float dy = s.y * ip - (T.y - s.y) * in_ + 1e-6f;
        float dz = s.z * ip - (T.z - s.z) * in_ + 1e-6f;
        float dw = s.w * ip - (T.w - s.w) * in_ + 1e-6f;
        partial = dx * dx + dy * dy + dz * dz + dw * dw;
    }

    red[t] = partial;
    __syncthreads();
    #pragma unroll
    for (int s2 = 64; s2 > 0; s2 >>= 1) {
        if (t < s2) red[t] += red[t + s2];
        __syncthreads();
    }
    if (t == 0) {
        float dist = sqrtf(red[0]);
        float m = fmaxf(1.0f - dist, 0.f);      // MARGIN = 1.0
        g_lossw[k] = (c > 0) ? (float)c * m * m : 0.f;
    }
}

// ---------------------------------------------------------------------------
// K3c: deterministic final reduction of 512 class losses -> scalar mean.
// ---------------------------------------------------------------------------
__global__ void k_final(float* __restrict__ out, float fN)
{
    __shared__ float red[NCLS];
    int t = threadIdx.x;
    red[t] = g_lossw[t];
    __syncthreads();
    #pragma unroll
    for (int s = NCLS / 2; s > 0; s >>= 1) {
        if (t < s) red[t] += red[t + s];
        __syncthreads();
    }
    if (t == 0) out[0] = red[0] / fN;
}

// ---------------------------------------------------------------------------
extern "C" void kernel_launch(void* const* d_in, const int* in_sizes, int n_in,
                              void* d_out, int out_size)
{
    const float* output = (const float*)d_in[0];
    const int*   label  = (const int*)d_in[1];
    int N = in_sizes[1];

    k_zero<<<1, NCLS>>>();
    k_scatter<<<(N + 255) / 256, 256>>>(label, N);
    k_class_sum<<<NCLS, 256>>>(output);
    k_total_part<<<TSLB, 128>>>();
    k_loss<<<NCLS, 128>>>((float)N);
    k_final<<<1, NCLS>>>((float*)d_out, (float)N);
}

// round 4
// speedup vs baseline: 1.4691x; 1.0916x over previous
#include <cuda_runtime.h>

// ScatterLoss — per-class contrastive hinge loss.
// d_in[0] = output [N, D] float32 (N=65536, D=512)
// d_in[1] = label_id [N] int32
// out     = scalar float32
//
// loss = (1/N) * sum_k cnt_k * relu(1 - || s_k/c_k - (T - s_k)/(N - c_k) + 1e-6 ||_2)^2

#define NCLS 512
#define DDIM 512
#define NF4  (DDIM / 4)   // 128 float4 columns
#define CAP  1024         // max rows per class (counts ~128±11)

static __device__ int   g_cnt[NCLS];
static __device__ int   g_idx[NCLS * CAP];
static __device__ float g_sumsp[2][NCLS][DDIM];  // per-half partial class sums
static __device__ float g_total[DDIM];

// ---------------------------------------------------------------------------
// K0: zero per-class counters + output scalar (graph replays need reset).
// ---------------------------------------------------------------------------
__global__ void k_zero(float* __restrict__ out)
{
    g_cnt[threadIdx.x] = 0;
    if (threadIdx.x == 0) out[0] = 0.f;
}

// ---------------------------------------------------------------------------
// K1: counting-sort scatter — per-class row-index lists.
// ---------------------------------------------------------------------------
__global__ void k_scatter(const int* __restrict__ lab, int N)
{
    int i = blockIdx.x * blockDim.x + threadIdx.x;
    if (i < N) {
        int k = lab[i];
        if (k >= 0 && k < NCLS) {
            int pos = atomicAdd(&g_cnt[k], 1);
            if (pos < CAP) g_idx[k * CAP + pos] = i;
        }
    }
}

// ---------------------------------------------------------------------------
// K2: per-class partial sums. Two CTAs per class (contiguous halves of the
// row list) -> 1024 CTAs for wave balance; 128 threads = one float4 column
// each; 2KB fully-coalesced row reads; unroll 8 for MLP.
// Reads the full 128 MB matrix exactly once -> HBM bound (dominant kernel).
// ---------------------------------------------------------------------------
__global__ void __launch_bounds__(128) k_class_sum_half(const float* __restrict__ out)
{
    __shared__ int srows[CAP / 2 + 1];

    int k  = blockIdx.x >> 1;
    int h  = blockIdx.x & 1;
    int nk = min(g_cnt[k], CAP);
    int j0 = h ? (nk >> 1) : 0;
    int j1 = h ? nk : (nk >> 1);
    int nj = j1 - j0;

    for (int j = threadIdx.x; j < nj; j += blockDim.x)
        srows[j] = g_idx[k * CAP + j0 + j];
    __syncthreads();

    int q = threadIdx.x;  // float4 column 0..127

    float4 acc = make_float4(0.f, 0.f, 0.f, 0.f);
    #pragma unroll 8
    for (int j = 0; j < nj; j++) {
        const float4* row = (const float4*)(out + (size_t)srows[j] * DDIM);
        float4 v = __ldg(row + q);
        acc.x += v.x; acc.y += v.y; acc.z += v.z; acc.w += v.w;
    }
    ((float4*)g_sumsp[h][k])[q] = acc;
}

// ---------------------------------------------------------------------------
// K3: grand total. One block per float4 column (128 blocks x 128 threads);
// thread t folds classes {t, t+128, t+256, t+384} x both halves (8 loads,
// all L2-resident), then smem tree-reduce -> T[col].
// ---------------------------------------------------------------------------
__global__ void __launch_bounds__(128) k_total()
{
    __shared__ float4 red[128];
    int col = blockIdx.x;
    int t   = threadIdx.x;

    float4 acc = make_float4(0.f, 0.f, 0.f, 0.f);
    #pragma unroll
    for (int j = 0; j < 4; j++) {
        int k = t + j * 128;
        float4 a = ((const float4*)g_sumsp[0][k])[col];
        float4 b = ((const float4*)g_sumsp[1][k])[col];
        acc.x += a.x + b.x; acc.y += a.y + b.y;
        acc.z += a.z + b.z; acc.w += a.w + b.w;
    }
    red[t] = acc;
    __syncthreads();
    #pragma unroll
    for (int s = 64; s > 0; s >>= 1) {
        if (t < s) {
            float4 b = red[t + s];
            red[t].x += b.x; red[t].y += b.y; red[t].z += b.z; red[t].w += b.w;
        }
        __syncthreads();
    }
    if (t == 0) ((float4*)g_total)[col] = red[0];
}

// ---------------------------------------------------------------------------
// K4: per-class hinge loss, weighted by count, accumulated straight into the
// output scalar (one atomicAdd per class block; d_out pre-zeroed).
// ---------------------------------------------------------------------------
__global__ void __launch_bounds__(128) k_loss(float* __restrict__ out, float fN)
{
    __shared__ float red[128];
    int k = blockIdx.x;
    int t = threadIdx.x;
    int c = g_cnt[k];

    float partial = 0.f;
    if (c > 0) {
        float fc  = (float)c;
        float ip  = 1.f / fc;
        float in_ = 1.f / (fN - fc);
        float4 a = ((const float4*)g_sumsp[0][k])[t];
        float4 b = ((const float4*)g_sumsp[1][k])[t];
        float4 T = ((const float4*)g_total)[t];
        float sx = a.x + b.x, sy = a.y + b.y, sz = a.z + b.z, sw = a.w + b.w;
        float dx = sx * ip - (T.x - sx) * in_ + 1e-6f;
        float dy = sy * ip - (T.y - sy) * in_ + 1e-6f;
        float dz = sz * ip - (T.z - sz) * in_ + 1e-6f;
        float dw = sw * ip - (T.w - sw) * in_ + 1e-6f;
        partial = dx * dx + dy * dy + dz * dz + dw * dw;
    }

    red[t] = partial;
    __syncthreads();
    #pragma unroll
    for (int s2 = 64; s2 > 0; s2 >>= 1) {
        if (t < s2) red[t] += red[t + s2];
        __syncthreads();
    }
    if (t == 0 && c > 0) {
        float dist = sqrtf(red[0]);
        float m = fmaxf(1.0f - dist, 0.f);      // MARGIN = 1.0
        float w = (float)c * m * m / fN;
        if (w != 0.f) atomicAdd(out, w);
    }
}

// ---------------------------------------------------------------------------
extern "C" void kernel_launch(void* const* d_in, const int* in_sizes, int n_in,
                              void* d_out, int out_size)
{
    const float* output = (const float*)d_in[0];
    const int*   label  = (const int*)d_in[1];
    int N = in_sizes[1];

    k_zero<<<1, NCLS>>>((float*)d_out);
    k_scatter<<<(N + 255) / 256, 256>>>(label, N);
    k_class_sum_half<<<NCLS * 2, 128>>>(output);
    k_total<<<NF4, 128>>>();
    k_loss<<<NCLS, 128>>>((float*)d_out, (float)N);
}